// round 1
// baseline (speedup 1.0000x reference)
#include <cuda_runtime.h>
#include <math.h>

#define Bb 2
#define Tt 2048
#define Dd 1024
#define Hh 16
#define DHh 64
#define D3 3072
#define NT 4096      // B*T
#define QT 16        // query rows per attention block

// scratch (no allocations allowed)
__device__ float g_qkv[(size_t)NT * D3];   // [B,T,3D]
__device__ float g_att[(size_t)NT * Dd];   // [B,T,H,DH] == [B,T,D]

// ---------------------------------------------------------------------------
// 64x64 tiled fp32 GEMM: C[M,N] = A[M,K] @ B[K,N] (+ bias), all row-major.
// 256 threads, 4x4 per thread, BK=16.
// ---------------------------------------------------------------------------
__global__ __launch_bounds__(256) void gemm64(const float* __restrict__ A,
                                              const float* __restrict__ Bm,
                                              const float* __restrict__ bias,
                                              float* __restrict__ C,
                                              int M, int N, int K) {
    __shared__ float As[64 * 16];      // As[m][k]
    __shared__ float Bs[16 * 64];      // Bs[k][n]
    const int tid = threadIdx.x;
    const int tx = tid & 15, ty = tid >> 4;
    const int m0 = blockIdx.y * 64, n0 = blockIdx.x * 64;

    float c[4][4] = {};

    for (int k0 = 0; k0 < K; k0 += 16) {
        #pragma unroll
        for (int p = 0; p < 4; p++) {
            int e = p * 256 + tid;
            int m = e >> 4, kk = e & 15;
            As[m * 16 + kk] = A[(size_t)(m0 + m) * K + (k0 + kk)];
        }
        #pragma unroll
        for (int p = 0; p < 4; p++) {
            int e = p * 256 + tid;
            int kk = e >> 6, n = e & 63;
            Bs[kk * 64 + n] = Bm[(size_t)(k0 + kk) * N + (n0 + n)];
        }
        __syncthreads();

        #pragma unroll
        for (int kk = 0; kk < 16; kk++) {
            float a0 = As[(ty * 4 + 0) * 16 + kk];
            float a1 = As[(ty * 4 + 1) * 16 + kk];
            float a2 = As[(ty * 4 + 2) * 16 + kk];
            float a3 = As[(ty * 4 + 3) * 16 + kk];
            float4 b = *(const float4*)&Bs[kk * 64 + tx * 4];
            c[0][0] += a0 * b.x; c[0][1] += a0 * b.y; c[0][2] += a0 * b.z; c[0][3] += a0 * b.w;
            c[1][0] += a1 * b.x; c[1][1] += a1 * b.y; c[1][2] += a1 * b.z; c[1][3] += a1 * b.w;
            c[2][0] += a2 * b.x; c[2][1] += a2 * b.y; c[2][2] += a2 * b.z; c[2][3] += a2 * b.w;
            c[3][0] += a3 * b.x; c[3][1] += a3 * b.y; c[3][2] += a3 * b.z; c[3][3] += a3 * b.w;
        }
        __syncthreads();
    }

    float4 bv = make_float4(0.f, 0.f, 0.f, 0.f);
    if (bias) bv = *(const float4*)&bias[n0 + tx * 4];
    #pragma unroll
    for (int i = 0; i < 4; i++) {
        float4 v;
        v.x = c[i][0] + bv.x;
        v.y = c[i][1] + bv.y;
        v.z = c[i][2] + bv.z;
        v.w = c[i][3] + bv.w;
        *(float4*)&C[(size_t)(m0 + ty * 4 + i) * N + (n0 + tx * 4)] = v;
    }
}

// ---------------------------------------------------------------------------
// Fused causal attention: per block = one (b,h) and 16 query rows.
// Full score rows (16 x 2048 fp32) held in smem -> exact softmax, single
// weights write, PV from smem probabilities.
// ---------------------------------------------------------------------------
#define KV_STRIDE 65
#define SMEM_FLOATS (QT * Tt + QT * DHh + 64 * KV_STRIDE)

__global__ __launch_bounds__(256) void attn_kernel(const float* __restrict__ qkv,
                                                   float* __restrict__ attout,
                                                   float* __restrict__ wout) {
    extern __shared__ float sm[];
    float* sc = sm;                       // [QT][Tt]
    float* qs = sc + QT * Tt;             // [QT][DHh]
    float* kv = qs + QT * DHh;            // [64][KV_STRIDE]

    const int tid = threadIdx.x;
    const int bid = blockIdx.x;
    const int qt = bid & 127;             // T/QT = 128 tiles
    const int bh = bid >> 7;
    const int b = bh >> 4, h = bh & 15;
    const int q0 = qt * QT;
    const int r = tid >> 4;               // query row within tile (0..15)
    const int lane = tid & 15;
    const int qrow = q0 + r;              // global query index
    const int ntile = (q0 + QT + 63) >> 6;  // number of 64-key tiles needed
    const int lim = ntile * 64;

    const float* base = qkv + (size_t)b * Tt * D3;

    // load Q tile: qs[rr][d]
    for (int e = tid; e < QT * DHh; e += 256) {
        int rr = e >> 6, d = e & 63;
        qs[e] = base[(size_t)(q0 + rr) * D3 + h * DHh + d];
    }

    // ---- phase 1: raw scores into sc ----
    for (int kt = 0; kt < ntile; kt++) {
        for (int e = tid; e < 64 * DHh; e += 256) {
            int d = e & 63, cc = e >> 6;
            kv[cc * KV_STRIDE + d] = base[(size_t)(kt * 64 + cc) * D3 + Dd + h * DHh + d];
        }
        __syncthreads();
        float acc[4] = {0.f, 0.f, 0.f, 0.f};
        #pragma unroll 4
        for (int d = 0; d < DHh; d++) {
            float qv = qs[r * DHh + d];
            #pragma unroll
            for (int j = 0; j < 4; j++)
                acc[j] += qv * kv[(lane + 16 * j) * KV_STRIDE + d];
        }
        #pragma unroll
        for (int j = 0; j < 4; j++) {
            int kg = kt * 64 + lane + 16 * j;
            sc[r * Tt + kg] = acc[j] * 0.125f;   // 1/sqrt(64)
        }
        __syncthreads();
    }

    // ---- phase 2: softmax over [0, qrow], zero masked up to lim ----
    {
        float m = -INFINITY;
        for (int k = lane; k <= qrow; k += 16) m = fmaxf(m, sc[r * Tt + k]);
        #pragma unroll
        for (int o = 8; o; o >>= 1) m = fmaxf(m, __shfl_xor_sync(0xffffffffu, m, o));
        float s = 0.f;
        for (int k = lane; k <= qrow; k += 16) {
            float e = __expf(sc[r * Tt + k] - m);
            sc[r * Tt + k] = e;
            s += e;
        }
        #pragma unroll
        for (int o = 8; o; o >>= 1) s += __shfl_xor_sync(0xffffffffu, s, o);
        float inv = 1.f / s;
        for (int k = lane; k < lim; k += 16)
            sc[r * Tt + k] = (k <= qrow) ? sc[r * Tt + k] * inv : 0.f;
    }
    __syncthreads();

    // ---- phase 3a: write normalized weights (float4, coalesced) ----
    {
        float4* wrow = (float4*)(wout + ((size_t)bh * Tt + qrow) * Tt);
        const float4* srow = (const float4*)(sc + r * Tt);
        for (int k4 = lane; k4 < Tt / 4; k4 += 16)
            wrow[k4] = (k4 * 4 < lim) ? srow[k4] : make_float4(0.f, 0.f, 0.f, 0.f);
    }

    // ---- phase 3b: PV ----
    float acc[4] = {0.f, 0.f, 0.f, 0.f};
    for (int kt = 0; kt < ntile; kt++) {
        __syncthreads();   // weights write above reads sc; also previous compute
        for (int e = tid; e < 64 * DHh; e += 256) {
            int d = e & 63, cc = e >> 6;
            kv[cc * KV_STRIDE + d] = base[(size_t)(kt * 64 + cc) * D3 + 2 * Dd + h * DHh + d];
        }
        __syncthreads();
        #pragma unroll 4
        for (int kk = 0; kk < 64; kk++) {
            float w = sc[r * Tt + kt * 64 + kk];
            #pragma unroll
            for (int j = 0; j < 4; j++)
                acc[j] += w * kv[kk * KV_STRIDE + lane + 16 * j];
        }
    }
    // att layout [B,T,H,DH] == [B,T,D]
    #pragma unroll
    for (int j = 0; j < 4; j++)
        attout[((size_t)(b * Tt + qrow) * Hh + h) * DHh + lane + 16 * j] = acc[j];
}

// ---------------------------------------------------------------------------

extern "C" void kernel_launch(void* const* d_in, const int* in_sizes, int n_in,
                              void* d_out, int out_size) {
    const float* x    = (const float*)d_in[0];
    // d_in[1] = attn_mask (causal; structure known, not read)
    const float* Wqkv = (const float*)d_in[2];
    const float* Wo   = (const float*)d_in[3];
    const float* bo   = (const float*)d_in[4];

    float* out = (float*)d_out;                       // [B,T,D]
    float* wts = out + (size_t)NT * Dd;               // [B,H,T,T]

    float* qkvp = nullptr; float* attp = nullptr;
    cudaGetSymbolAddress((void**)&qkvp, g_qkv);
    cudaGetSymbolAddress((void**)&attp, g_att);

    // 1) qkv = x @ Wqkv
    gemm64<<<dim3(D3 / 64, NT / 64), 256>>>(x, Wqkv, nullptr, qkvp, NT, D3, Dd);

    // 2) fused attention (scores + softmax + weights write + PV)
    size_t smem = (size_t)SMEM_FLOATS * sizeof(float);
    cudaFuncSetAttribute(attn_kernel, cudaFuncAttributeMaxDynamicSharedMemorySize, (int)smem);
    attn_kernel<<<Bb * Hh * (Tt / QT), 256, smem>>>(qkvp, attp, wts);

    // 3) out = att @ Wo + bo
    gemm64<<<dim3(Dd / 64, NT / 64), 256>>>(attp, Wo, bo, out, NT, Dd, Dd);
}

// round 4
// speedup vs baseline: 2.5150x; 2.5150x over previous
#include <cuda_runtime.h>
#include <cuda_bf16.h>
#include <cstdint>
#include <math.h>

#define Tt 2048
#define Dd 1024
#define Hh 16
#define D3 3072
#define NT 4096      // B*T
#define BHn 32       // B*H

typedef __nv_bfloat16 bf16;

// ---------------- scratch (no runtime allocation allowed) ----------------
__device__ float g_qkv[(size_t)NT * D3];        // [B,T,3D] fp32
__device__ float g_att[(size_t)NT * Dd];        // [B,T,D]  fp32
__device__ bf16  g_wt_hi[(size_t)D3 * Dd];      // Wqkv^T [3D, D]
__device__ bf16  g_wt_lo[(size_t)D3 * Dd];
__device__ bf16  g_wot_hi[(size_t)Dd * Dd];     // Wo^T [D, D]
__device__ bf16  g_wot_lo[(size_t)Dd * Dd];
__device__ bf16  g_vt_hi[(size_t)BHn * 64 * Tt];  // V^T per (b,h): [64, T]
__device__ bf16  g_vt_lo[(size_t)BHn * 64 * Tt];

// ---------------- helpers ----------------
__device__ __forceinline__ uint32_t smem_u32(const void* p) {
    uint32_t a;
    asm("{ .reg .u64 t; cvta.to.shared.u64 t, %1; cvt.u32.u64 %0, t; }" : "=r"(a) : "l"(p));
    return a;
}

#define LDSM_X4(r0, r1, r2, r3, a) \
    asm volatile("ldmatrix.sync.aligned.m8n8.x4.shared.b16 {%0,%1,%2,%3}, [%4];" \
                 : "=r"(r0), "=r"(r1), "=r"(r2), "=r"(r3) : "r"(a))

#define MMA16816(c, a, b) \
    asm volatile("mma.sync.aligned.m16n8k16.row.col.f32.bf16.bf16.f32 " \
                 "{%0,%1,%2,%3}, {%4,%5,%6,%7}, {%8,%9}, {%0,%1,%2,%3};" \
                 : "+f"((c)[0]), "+f"((c)[1]), "+f"((c)[2]), "+f"((c)[3]) \
                 : "r"((a)[0]), "r"((a)[1]), "r"((a)[2]), "r"((a)[3]), \
                   "r"((b)[0]), "r"((b)[1]))

__device__ __forceinline__ uint64_t pack4(bf16 a, bf16 b, bf16 c, bf16 d) {
    __nv_bfloat162 p0(a, b), p1(c, d);
    uint32_t u0 = *(uint32_t*)&p0, u1 = *(uint32_t*)&p1;
    return ((uint64_t)u1 << 32) | u0;
}

// load rows x BK fp32 tile, split into bf16 hi/lo smem tiles (padded rows)
template<int BK, int ROWB>
__device__ __forceinline__ void load_conv(uint32_t s_hi, uint32_t s_lo,
                                          const float* __restrict__ src,
                                          int stride, int rows) {
    const int C4 = BK / 4;
    for (int e = threadIdx.x; e < rows * C4; e += 256) {
        int r = e / C4, c = e % C4;
        float4 v = *(const float4*)(src + (size_t)r * stride + c * 4);
        bf16 h0 = __float2bfloat16(v.x), h1 = __float2bfloat16(v.y);
        bf16 h2 = __float2bfloat16(v.z), h3 = __float2bfloat16(v.w);
        bf16 l0 = __float2bfloat16(v.x - __bfloat162float(h0));
        bf16 l1 = __float2bfloat16(v.y - __bfloat162float(h1));
        bf16 l2 = __float2bfloat16(v.z - __bfloat162float(h2));
        bf16 l3 = __float2bfloat16(v.w - __bfloat162float(h3));
        uint32_t off = r * ROWB + c * 8;
        uint64_t hp = pack4(h0, h1, h2, h3), lp = pack4(l0, l1, l2, l3);
        asm volatile("st.shared.b64 [%0], %1;" :: "r"(s_hi + off), "l"(hp) : "memory");
        asm volatile("st.shared.b64 [%0], %1;" :: "r"(s_lo + off), "l"(lp) : "memory");
    }
}

// load rows x BK bf16 tile (preconverted) into padded smem
template<int BK, int ROWB>
__device__ __forceinline__ void load_pre(uint32_t s_dst, const bf16* __restrict__ src,
                                         int stride, int rows) {
    const int C8 = BK / 8;
    for (int e = threadIdx.x; e < rows * C8; e += 256) {
        int r = e / C8, c = e % C8;
        uint4 v = *(const uint4*)(src + (size_t)r * stride + c * 8);
        asm volatile("st.shared.v4.b32 [%0], {%1,%2,%3,%4};"
                     :: "r"(s_dst + (uint32_t)(r * ROWB + c * 16)),
                        "r"(v.x), "r"(v.y), "r"(v.z), "r"(v.w) : "memory");
    }
}

// one hi/lo source pass over NKB k16-chunks for a warp tile of MI*16 x NI*8
template<int MI, int NI, int NKB, int RA, int RB>
__device__ __forceinline__ void mma_pass(float (*acc)[NI][4], uint32_t sA, uint32_t sB,
                                         int lane, int m0, int n0) {
    #pragma unroll
    for (int kb = 0; kb < NKB; kb++) {
        uint32_t a[MI][4];
        #pragma unroll
        for (int mi = 0; mi < MI; mi++) {
            uint32_t ad = sA + (uint32_t)((m0 + mi * 16 + (lane & 15)) * RA
                                          + kb * 32 + ((lane >> 4) << 4));
            LDSM_X4(a[mi][0], a[mi][1], a[mi][2], a[mi][3], ad);
        }
        uint32_t b[NI][2];
        #pragma unroll
        for (int nb = 0; nb < NI / 2; nb++) {
            uint32_t ad = sB + (uint32_t)((n0 + nb * 16 + ((lane >> 4) << 3) + (lane & 7)) * RB
                                          + kb * 32 + (((lane >> 3) & 1) << 4));
            uint32_t r0, r1, r2, r3;
            LDSM_X4(r0, r1, r2, r3, ad);
            b[2 * nb][0] = r0; b[2 * nb][1] = r1;
            b[2 * nb + 1][0] = r2; b[2 * nb + 1][1] = r3;
        }
        #pragma unroll
        for (int mi = 0; mi < MI; mi++)
            #pragma unroll
            for (int ni = 0; ni < NI; ni++)
                MMA16816(acc[mi][ni], a[mi], b[ni]);
    }
}

// ---------------- kernels ----------------

// C[M,N] = A[M,K] @ B^T(hi/lo)[N,K] (+bias). 128x128 blocks, BK=32.
__global__ __launch_bounds__(256) void k_gemm(const float* __restrict__ A,
                                              const bf16* __restrict__ Bh,
                                              const bf16* __restrict__ Bl,
                                              const float* __restrict__ bias,
                                              float* __restrict__ C, int K, int N) {
    extern __shared__ char smem[];
    uint32_t sb = smem_u32(smem);
    const uint32_t sAh = sb, sAl = sb + 10240, sBh = sb + 20480, sBl = sb + 30720;
    const int tid = threadIdx.x, lane = tid & 31, wid = tid >> 5;
    const int m0 = blockIdx.y * 128, n0 = blockIdx.x * 128;
    const int wm = (wid >> 2) * 64, wn = (wid & 3) * 32;

    float acc[4][4][4];
    #pragma unroll
    for (int i = 0; i < 4; i++)
        #pragma unroll
        for (int j = 0; j < 4; j++)
            #pragma unroll
            for (int q = 0; q < 4; q++) acc[i][j][q] = 0.f;

    for (int k0 = 0; k0 < K; k0 += 32) {
        if (k0) __syncthreads();
        load_conv<32, 80>(sAh, sAl, A + (size_t)m0 * K + k0, K, 128);
        load_pre<32, 80>(sBh, Bh + (size_t)n0 * K + k0, K, 128);
        load_pre<32, 80>(sBl, Bl + (size_t)n0 * K + k0, K, 128);
        __syncthreads();
        mma_pass<4, 4, 2, 80, 80>(acc, sAh, sBh, lane, wm, wn);
        mma_pass<4, 4, 2, 80, 80>(acc, sAh, sBl, lane, wm, wn);
        mma_pass<4, 4, 2, 80, 80>(acc, sAl, sBh, lane, wm, wn);
    }

    #pragma unroll
    for (int mi = 0; mi < 4; mi++) {
        int r = m0 + wm + mi * 16 + (lane >> 2);
        #pragma unroll
        for (int ni = 0; ni < 4; ni++) {
            int c = n0 + wn + ni * 8 + (lane & 3) * 2;
            float bx = 0.f, by = 0.f;
            if (bias) { bx = bias[c]; by = bias[c + 1]; }
            *(float2*)&C[(size_t)r * N + c] =
                make_float2(acc[mi][ni][0] + bx, acc[mi][ni][1] + by);
            *(float2*)&C[(size_t)(r + 8) * N + c] =
                make_float2(acc[mi][ni][2] + bx, acc[mi][ni][3] + by);
        }
    }
}

// Scores: S = (Q . K)/8 for causal 128x128 tiles (tile i >= j). K-dim = 64.
__global__ __launch_bounds__(256) void k_scores(const float* __restrict__ qkv,
                                                float* __restrict__ wts) {
    extern __shared__ char smem[];
    uint32_t sb = smem_u32(smem);
    const uint32_t sAh = sb, sAl = sb + 18432, sBh = sb + 36864, sBl = sb + 55296;
    const int tid = threadIdx.x, lane = tid & 31, wid = tid >> 5;

    int t = blockIdx.x;
    int i = 0;
    while ((i + 1) * (i + 2) / 2 <= t) i++;
    int j = t - i * (i + 1) / 2;
    const int bh = blockIdx.y, b = bh >> 4, h = bh & 15;
    const float* base = qkv + (size_t)b * Tt * D3 + (size_t)h * 64;
    const float* Q = base + (size_t)(i * 128) * D3;
    const float* Kp = base + (size_t)(j * 128) * D3 + Dd;

    load_conv<64, 144>(sAh, sAl, Q, D3, 128);
    load_conv<64, 144>(sBh, sBl, Kp, D3, 128);
    __syncthreads();

    const int wm = (wid >> 2) * 64, wn = (wid & 3) * 32;
    float acc[4][4][4];
    #pragma unroll
    for (int a = 0; a < 4; a++)
        #pragma unroll
        for (int bq = 0; bq < 4; bq++)
            #pragma unroll
            for (int q = 0; q < 4; q++) acc[a][bq][q] = 0.f;

    mma_pass<4, 4, 4, 144, 144>(acc, sAh, sBh, lane, wm, wn);
    mma_pass<4, 4, 4, 144, 144>(acc, sAh, sBl, lane, wm, wn);
    mma_pass<4, 4, 4, 144, 144>(acc, sAl, sBh, lane, wm, wn);

    float* dstb = wts + ((size_t)bh * Tt + i * 128) * Tt + j * 128;
    #pragma unroll
    for (int mi = 0; mi < 4; mi++) {
        int r = wm + mi * 16 + (lane >> 2);
        #pragma unroll
        for (int ni = 0; ni < 4; ni++) {
            int c = wn + ni * 8 + (lane & 3) * 2;
            *(float2*)&dstb[(size_t)r * Tt + c] =
                make_float2(acc[mi][ni][0] * 0.125f, acc[mi][ni][1] * 0.125f);
            *(float2*)&dstb[(size_t)(r + 8) * Tt + c] =
                make_float2(acc[mi][ni][2] * 0.125f, acc[mi][ni][3] * 0.125f);
        }
    }
}

// PV: O[128q,64dh] = P @ V ; V^T hi/lo preconverted [64, T]
__global__ __launch_bounds__(256) void k_pv(const float* __restrict__ wts,
                                            const bf16* __restrict__ vh,
                                            const bf16* __restrict__ vl,
                                            float* __restrict__ att) {
    extern __shared__ char smem[];
    uint32_t sb = smem_u32(smem);
    const uint32_t sAh = sb, sAl = sb + 10240, sBh = sb + 20480, sBl = sb + 25600;
    const int tid = threadIdx.x, lane = tid & 31, wid = tid >> 5;
    const int i = blockIdx.x;
    const int bh = blockIdx.y, b = bh >> 4, h = bh & 15;
    const int nchunk = 4 * (i + 1);
    const float* W = wts + ((size_t)bh * Tt + i * 128) * Tt;
    const bf16* Vh = vh + (size_t)bh * 64 * Tt;
    const bf16* Vl = vl + (size_t)bh * 64 * Tt;
    const int wm = (wid >> 1) * 32, wn = (wid & 1) * 32;

    float acc[2][4][4];
    #pragma unroll
    for (int a = 0; a < 2; a++)
        #pragma unroll
        for (int bq = 0; bq < 4; bq++)
            #pragma unroll
            for (int q = 0; q < 4; q++) acc[a][bq][q] = 0.f;

    for (int c = 0; c < nchunk; c++) {
        if (c) __syncthreads();
        load_conv<32, 80>(sAh, sAl, W + c * 32, Tt, 128);
        load_pre<32, 80>(sBh, Vh + c * 32, Tt, 64);
        load_pre<32, 80>(sBl, Vl + c * 32, Tt, 64);
        __syncthreads();
        mma_pass<2, 4, 2, 80, 80>(acc, sAh, sBh, lane, wm, wn);
        mma_pass<2, 4, 2, 80, 80>(acc, sAh, sBl, lane, wm, wn);
        mma_pass<2, 4, 2, 80, 80>(acc, sAl, sBh, lane, wm, wn);
    }

    #pragma unroll
    for (int mi = 0; mi < 2; mi++) {
        int q = i * 128 + wm + mi * 16 + (lane >> 2);
        float* dst = att + ((size_t)b * Tt + q) * Dd + h * 64;
        float* dst8 = dst + (size_t)8 * Dd;
        #pragma unroll
        for (int ni = 0; ni < 4; ni++) {
            int c = wn + ni * 8 + (lane & 3) * 2;
            *(float2*)&dst[c]  = make_float2(acc[mi][ni][0], acc[mi][ni][1]);
            *(float2*)&dst8[c] = make_float2(acc[mi][ni][2], acc[mi][ni][3]);
        }
    }
}

// softmax over causal row; writes zeros beyond the diagonal
__global__ __launch_bounds__(256) void k_softmax(float* __restrict__ w) {
    const size_t row = blockIdx.x;
    const int q = (int)(row & (Tt - 1));
    float4* p = (float4*)(w + row * Tt);
    const int tid = threadIdx.x;
    __shared__ float red[8];

    float4 v[2];
    float m = -INFINITY;
    #pragma unroll
    for (int e = 0; e < 2; e++) {
        int k4 = e * 256 + tid;
        float4 t = p[k4];
        int k = k4 * 4;
        t.x = (k     <= q) ? t.x : -INFINITY;
        t.y = (k + 1 <= q) ? t.y : -INFINITY;
        t.z = (k + 2 <= q) ? t.z : -INFINITY;
        t.w = (k + 3 <= q) ? t.w : -INFINITY;
        v[e] = t;
        m = fmaxf(m, fmaxf(fmaxf(t.x, t.y), fmaxf(t.z, t.w)));
    }
    #pragma unroll
    for (int o = 16; o; o >>= 1) m = fmaxf(m, __shfl_xor_sync(0xffffffffu, m, o));
    if ((tid & 31) == 0) red[tid >> 5] = m;
    __syncthreads();
    m = fmaxf(fmaxf(fmaxf(red[0], red[1]), fmaxf(red[2], red[3])),
              fmaxf(fmaxf(red[4], red[5]), fmaxf(red[6], red[7])));
    __syncthreads();

    float s = 0.f;
    #pragma unroll
    for (int e = 0; e < 2; e++) {
        v[e].x = __expf(v[e].x - m);
        v[e].y = __expf(v[e].y - m);
        v[e].z = __expf(v[e].z - m);
        v[e].w = __expf(v[e].w - m);
        s += v[e].x + v[e].y + v[e].z + v[e].w;
    }
    #pragma unroll
    for (int o = 16; o; o >>= 1) s += __shfl_xor_sync(0xffffffffu, s, o);
    if ((tid & 31) == 0) red[tid >> 5] = s;
    __syncthreads();
    s = red[0] + red[1] + red[2] + red[3] + red[4] + red[5] + red[6] + red[7];
    float inv = 1.f / s;
    #pragma unroll
    for (int e = 0; e < 2; e++) {
        int k4 = e * 256 + tid;
        float4 t = v[e];
        t.x *= inv; t.y *= inv; t.z *= inv; t.w *= inv;
        p[k4] = t;
    }
}

// transpose + split-convert weight matrix: W[K,N] -> hi/lo [N,K]
__global__ __launch_bounds__(256) void k_conv_w(const float* __restrict__ W,
                                                bf16* __restrict__ hi, bf16* __restrict__ lo,
                                                int K, int N) {
    __shared__ float tile[32][33];
    const int n0 = blockIdx.x * 32, k0 = blockIdx.y * 32;
    const int tx = threadIdx.x & 31, ty = threadIdx.x >> 5;
    for (int r = ty; r < 32; r += 8) tile[r][tx] = W[(size_t)(k0 + r) * N + n0 + tx];
    __syncthreads();
    for (int r = ty; r < 32; r += 8) {
        float v = tile[tx][r];              // = W[k0+tx][n0+r]
        size_t o = (size_t)(n0 + r) * K + k0 + tx;
        bf16 h = __float2bfloat16(v);
        hi[o] = h;
        lo[o] = __float2bfloat16(v - __bfloat162float(h));
    }
}

// transpose + split-convert V from qkv: Vt[b,h][dh][t]
__global__ __launch_bounds__(256) void k_conv_vt(const float* __restrict__ qkv,
                                                 bf16* __restrict__ hi, bf16* __restrict__ lo) {
    __shared__ float tile[32][33];
    const int bh = blockIdx.z, b = bh >> 4, h = bh & 15;
    const int t0 = blockIdx.x * 32, d0 = blockIdx.y * 32;
    const int tx = threadIdx.x & 31, ty = threadIdx.x >> 5;
    const float* src = qkv + (size_t)b * Tt * D3 + 2 * Dd + (size_t)h * 64;
    for (int r = ty; r < 32; r += 8) tile[r][tx] = src[(size_t)(t0 + r) * D3 + d0 + tx];
    __syncthreads();
    bf16* oh = hi + (size_t)bh * 64 * Tt;
    bf16* ol = lo + (size_t)bh * 64 * Tt;
    for (int r = ty; r < 32; r += 8) {
        float v = tile[tx][r];              // = V[t0+tx][d0+r]
        size_t o = (size_t)(d0 + r) * Tt + t0 + tx;
        bf16 hh = __float2bfloat16(v);
        oh[o] = hh;
        ol[o] = __float2bfloat16(v - __bfloat162float(hh));
    }
}

// ---------------------------------------------------------------------------
extern "C" void kernel_launch(void* const* d_in, const int* in_sizes, int n_in,
                              void* d_out, int out_size) {
    const float* x    = (const float*)d_in[0];
    const float* Wqkv = (const float*)d_in[2];
    const float* Wo   = (const float*)d_in[3];
    const float* bo   = (const float*)d_in[4];

    float* out = (float*)d_out;                 // [B,T,D]
    float* wts = out + (size_t)NT * Dd;         // [B,H,T,T]

    float *qkvp, *attp;
    bf16 *wth, *wtl, *woth, *wotl, *vth, *vtl;
    cudaGetSymbolAddress((void**)&qkvp, g_qkv);
    cudaGetSymbolAddress((void**)&attp, g_att);
    cudaGetSymbolAddress((void**)&wth, g_wt_hi);
    cudaGetSymbolAddress((void**)&wtl, g_wt_lo);
    cudaGetSymbolAddress((void**)&woth, g_wot_hi);
    cudaGetSymbolAddress((void**)&wotl, g_wot_lo);
    cudaGetSymbolAddress((void**)&vth, g_vt_hi);
    cudaGetSymbolAddress((void**)&vtl, g_vt_lo);

    cudaFuncSetAttribute(k_scores, cudaFuncAttributeMaxDynamicSharedMemorySize, 73728);
    cudaFuncSetAttribute(k_gemm,   cudaFuncAttributeMaxDynamicSharedMemorySize, 40960);
    cudaFuncSetAttribute(k_pv,     cudaFuncAttributeMaxDynamicSharedMemorySize, 30720);

    // weight prepasses
    k_conv_w<<<dim3(D3 / 32, Dd / 32), 256>>>(Wqkv, wth, wtl, Dd, D3);
    k_conv_w<<<dim3(Dd / 32, Dd / 32), 256>>>(Wo, woth, wotl, Dd, Dd);

    // 1) QKV projection
    k_gemm<<<dim3(D3 / 128, NT / 128), 256, 40960>>>(x, wth, wtl, nullptr, qkvp, Dd, D3);

    // 2) V transpose/convert
    k_conv_vt<<<dim3(Tt / 32, 2, BHn), 256>>>(qkvp, vth, vtl);

    // 3) causal score tiles (raw, scaled)
    k_scores<<<dim3(136, BHn), 256, 73728>>>(qkvp, wts);

    // 4) softmax (writes final weights incl. zero tail)
    k_softmax<<<BHn * Tt, 256>>>(wts);

    // 5) PV
    k_pv<<<dim3(Tt / 128, BHn), 256, 30720>>>(wts, vth, vtl, attp);

    // 6) O projection
    k_gemm<<<dim3(Dd / 128, NT / 128), 256, 40960>>>(attp, woth, wotl, bo, out, Dd, Dd);
}